// round 9
// baseline (speedup 1.0000x reference)
#include <cuda_runtime.h>
#include <cuda_bf16.h>
#include <cstdint>

typedef unsigned long long u64;
typedef unsigned int u32;

#define NN 16384

// ---------------------------------------------------------------------------
// Scratch (static device globals — no runtime allocation allowed)
// ---------------------------------------------------------------------------
__device__ float g_h1[(size_t)NN * 512];
__device__ float g_h2[(size_t)NN * 256];
__device__ float g_h3[(size_t)NN * 256];
__device__ float g_h4[(size_t)NN * 128];
__device__ float g_dis[NN];
// split-bf16 B operands, stored [N][K] (K-major)
__device__ __nv_bfloat16 g_t1h[(size_t)256 * NN];
__device__ __nv_bfloat16 g_t1l[(size_t)256 * NN];
__device__ __nv_bfloat16 g_t2h[(size_t)128 * NN];
__device__ __nv_bfloat16 g_t2l[(size_t)128 * NN];
__device__ __nv_bfloat16 g_w1h[(size_t)512 * 1024];
__device__ __nv_bfloat16 g_w1l[(size_t)512 * 1024];
__device__ __nv_bfloat16 g_w2h[(size_t)256 * 512];
__device__ __nv_bfloat16 g_w2l[(size_t)256 * 512];
__device__ __nv_bfloat16 g_g1h[(size_t)256 * 256];
__device__ __nv_bfloat16 g_g1l[(size_t)256 * 256];
__device__ __nv_bfloat16 g_g2h[(size_t)128 * 256];
__device__ __nv_bfloat16 g_g2l[(size_t)128 * 256];

// ---------------------------------------------------------------------------
// helpers
// ---------------------------------------------------------------------------
static __device__ __forceinline__ u32 cvt2(float lo, float hi) {
    u32 r;  // result: low 16 bits <- lo, high 16 bits <- hi
    asm("cvt.rn.bf16x2.f32 %0, %1, %2;" : "=r"(r) : "f"(hi), "f"(lo));
    return r;
}
// mma.sync m16n8k16 row.col bf16 -> f32 accumulate (base-target instruction,
// compiles at compute_103; tcgen05 is sm_103a-only and rejected by this bench)
static __device__ __forceinline__ void mma16816(float* d, const u32* a, const u32* b) {
    asm volatile(
        "mma.sync.aligned.m16n8k16.row.col.f32.bf16.bf16.f32 "
        "{%0,%1,%2,%3}, {%4,%5,%6,%7}, {%8,%9}, {%0,%1,%2,%3};"
        : "+f"(d[0]), "+f"(d[1]), "+f"(d[2]), "+f"(d[3])
        : "r"(a[0]), "r"(a[1]), "r"(a[2]), "r"(a[3]), "r"(b[0]), "r"(b[1]));
}

// ---------------------------------------------------------------------------
// GEMM: C[128x128 tile] = A[M x K](fp32, split on the fly) @ B^T
// B pre-split bf16 hi/lo in global, layout [Nt][K] (K-major).
// 3 passes in fp32 accumulators: Ah*Bh + Ah*Bl + Al*Bh  (Al*Bl ~2^-16, dropped)
// smem: padded K-major tiles [row][40] bf16 (80B rows -> conflict-free frags)
// EPI 0: BN-eval+ReLU -> C fp32            (p0=b, p1=g, p2=beta, p3=m, p4=v)
// EPI 1: v*dis[row] -> split bf16 Th/Tl stored [col][NN]          (p0=dis)
// EPI 2: relu(v*dis[row] + p1[col]) -> C fp32                     (p0=dis)
// ---------------------------------------------------------------------------
#define PAD 40

template<int EPI>
__global__ void __launch_bounds__(256)
mma_gemm(const float* __restrict__ A, int lda,
         const __nv_bfloat16* __restrict__ Bh, const __nv_bfloat16* __restrict__ Bl,
         int K, int Nt, float* __restrict__ C,
         __nv_bfloat16* __restrict__ Th, __nv_bfloat16* __restrict__ Tl,
         const float* __restrict__ p0, const float* __restrict__ p1,
         const float* __restrict__ p2, const float* __restrict__ p3,
         const float* __restrict__ p4)
{
    __shared__ __nv_bfloat16 sAh[128 * PAD];
    __shared__ __nv_bfloat16 sAl[128 * PAD];
    __shared__ __nv_bfloat16 sBh[128 * PAD];
    __shared__ __nv_bfloat16 sBl[128 * PAD];

    const int tid  = threadIdx.x;
    const int lane = tid & 31;
    const int wid  = tid >> 5;
    const int g    = lane >> 2;   // group id 0..7
    const int t    = lane & 3;    // thread-in-group 0..3
    const int wm   = wid & 1;     // warp m half (0/1)  -> rows wm*64..+63
    const int wn   = wid >> 1;    // warp n quarter     -> cols wn*32..+31
    const int m0   = blockIdx.x * 128;
    const int n0   = blockIdx.y * 128;

    float acc[4][4][4];
    #pragma unroll
    for (int i = 0; i < 4; i++)
        #pragma unroll
        for (int j = 0; j < 4; j++)
            #pragma unroll
            for (int k = 0; k < 4; k++) acc[i][j][k] = 0.f;

    const int nch = K >> 5;
    for (int c = 0; c < nch; ++c) {
        const int k0 = c << 5;

        // ---- fill A tile: 128x32 fp32 -> bf16 hi/lo (4 float4 per thread) ----
        #pragma unroll
        for (int it = 0; it < 4; ++it) {
            const int idx = it * 256 + tid;
            const int row = idx >> 3, q = idx & 7;
            const float4 v = *(const float4*)(A + (size_t)(m0 + row) * lda + k0 + q * 4);
            const u32 h01 = cvt2(v.x, v.y);
            const u32 h23 = cvt2(v.z, v.w);
            const float l0 = v.x - __uint_as_float(h01 << 16);
            const float l1 = v.y - __uint_as_float(h01 & 0xFFFF0000u);
            const float l2 = v.z - __uint_as_float(h23 << 16);
            const float l3 = v.w - __uint_as_float(h23 & 0xFFFF0000u);
            *(u64*)&sAh[row * PAD + q * 4] = ((u64)h23 << 32) | h01;
            *(u64*)&sAl[row * PAD + q * 4] = ((u64)cvt2(l2, l3) << 32) | cvt2(l0, l1);
        }
        // ---- fill B tiles: 128x32 bf16 hi/lo (4 u64 per thread each) ----
        #pragma unroll
        for (int it = 0; it < 4; ++it) {
            const int idx = it * 256 + tid;
            const int n = idx >> 3, q = idx & 7;
            const size_t gaddr = (size_t)(n0 + n) * K + k0 + q * 4;
            *(u64*)&sBh[n * PAD + q * 4] = *(const u64*)(Bh + gaddr);
            *(u64*)&sBl[n * PAD + q * 4] = *(const u64*)(Bl + gaddr);
        }
        __syncthreads();

        #pragma unroll
        for (int ko = 0; ko < 32; ko += 16) {
            u32 af[4][4], bh_[4][2], bl_[4][2];
            #pragma unroll
            for (int mt = 0; mt < 4; ++mt) {
                const int r = wm * 64 + mt * 16 + g;
                af[mt][0] = *(const u32*)&sAh[r * PAD + ko + 2 * t];
                af[mt][1] = *(const u32*)&sAh[(r + 8) * PAD + ko + 2 * t];
                af[mt][2] = *(const u32*)&sAh[r * PAD + ko + 8 + 2 * t];
                af[mt][3] = *(const u32*)&sAh[(r + 8) * PAD + ko + 8 + 2 * t];
            }
            #pragma unroll
            for (int nt = 0; nt < 4; ++nt) {
                const int r = wn * 32 + nt * 8 + g;
                bh_[nt][0] = *(const u32*)&sBh[r * PAD + ko + 2 * t];
                bh_[nt][1] = *(const u32*)&sBh[r * PAD + ko + 8 + 2 * t];
                bl_[nt][0] = *(const u32*)&sBl[r * PAD + ko + 2 * t];
                bl_[nt][1] = *(const u32*)&sBl[r * PAD + ko + 8 + 2 * t];
            }
            // pass 1+2: Ah*Bh, Ah*Bl
            #pragma unroll
            for (int mt = 0; mt < 4; ++mt)
                #pragma unroll
                for (int nt = 0; nt < 4; ++nt) {
                    mma16816(acc[mt][nt], af[mt], bh_[nt]);
                    mma16816(acc[mt][nt], af[mt], bl_[nt]);
                }
            // pass 3: Al*Bh (reuse af registers)
            #pragma unroll
            for (int mt = 0; mt < 4; ++mt) {
                const int r = wm * 64 + mt * 16 + g;
                af[mt][0] = *(const u32*)&sAl[r * PAD + ko + 2 * t];
                af[mt][1] = *(const u32*)&sAl[(r + 8) * PAD + ko + 2 * t];
                af[mt][2] = *(const u32*)&sAl[r * PAD + ko + 8 + 2 * t];
                af[mt][3] = *(const u32*)&sAl[(r + 8) * PAD + ko + 8 + 2 * t];
            }
            #pragma unroll
            for (int mt = 0; mt < 4; ++mt)
                #pragma unroll
                for (int nt = 0; nt < 4; ++nt)
                    mma16816(acc[mt][nt], af[mt], bh_[nt]);
        }
        __syncthreads();
    }

    // ---- epilogue ----
    #pragma unroll
    for (int mt = 0; mt < 4; ++mt) {
        #pragma unroll
        for (int i2 = 0; i2 < 2; ++i2) {          // row sub: g / g+8
            const int row = m0 + wm * 64 + mt * 16 + g + i2 * 8;
            float disv = 0.f;
            if (EPI == 1 || EPI == 2) disv = p0[row];
            #pragma unroll
            for (int nt = 0; nt < 4; ++nt) {
                #pragma unroll
                for (int j2 = 0; j2 < 2; ++j2) {  // col sub: 2t / 2t+1
                    const int col = n0 + wn * 32 + nt * 8 + 2 * t + j2;
                    float v = acc[mt][nt][i2 * 2 + j2];
                    if (EPI == 0) {
                        const float s = p1[col] * rsqrtf(p4[col] + 1e-5f);
                        v = fmaxf(fmaf(v + p0[col] - p3[col], s, p2[col]), 0.0f);
                        C[(size_t)row * Nt + col] = v;
                    } else if (EPI == 1) {
                        v *= disv;
                        const __nv_bfloat16 h = __float2bfloat16(v);
                        Th[(size_t)col * NN + row] = h;
                        Tl[(size_t)col * NN + row] =
                            __float2bfloat16(v - __bfloat162float(h));
                    } else {
                        v = fmaxf(fmaf(v, disv, p1[col]), 0.0f);
                        C[(size_t)row * Nt + col] = v;
                    }
                }
            }
        }
    }
}

// ---------------------------------------------------------------------------
// Weight convert+transpose+split: in [K][N] fp32 -> oh/ol [N][K] bf16
// ---------------------------------------------------------------------------
__global__ void convT(const float* __restrict__ in, int K, int N,
                      __nv_bfloat16* __restrict__ oh, __nv_bfloat16* __restrict__ ol)
{
    const int j = blockIdx.x * 256 + threadIdx.x;   // j over N*K, k fastest
    const int n = j / K, k = j % K;
    const float v = in[(size_t)k * N + n];
    const __nv_bfloat16 h = __float2bfloat16(v);
    oh[j] = h;
    ol[j] = __float2bfloat16(v - __bfloat162float(h));
}

// ---------------------------------------------------------------------------
// deg kernel: dis[row] = rsqrt(sum_j adj[row][j])
// ---------------------------------------------------------------------------
__global__ void deg_kernel(const float* __restrict__ adj, float* __restrict__ dis) {
    const int row = blockIdx.x;
    const float4* a = (const float4*)(adj + (size_t)row * NN);
    float s = 0.f;
    for (int i = threadIdx.x; i < NN / 4; i += 256) {
        float4 v = a[i];
        s += (v.x + v.y) + (v.z + v.w);
    }
    __shared__ float red[256];
    red[threadIdx.x] = s;
    __syncthreads();
    #pragma unroll
    for (int st = 128; st > 0; st >>= 1) {
        if (threadIdx.x < st) red[threadIdx.x] += red[threadIdx.x + st];
        __syncthreads();
    }
    if (threadIdx.x == 0) dis[row] = rsqrtf(red[0]);
}

// ---------------------------------------------------------------------------
// Classifier: out = clip(sigmoid(h4[NNx128] @ cls_w[128x10] + cls_b))
// ---------------------------------------------------------------------------
__global__ void cls_kernel(const float* __restrict__ H, const float* __restrict__ W,
                           const float* __restrict__ Bv, float* __restrict__ out)
{
    __shared__ float ws[128 * 10];
    __shared__ float bs[10];
    const int tid = threadIdx.x;
    for (int i = tid; i < 128 * 10; i += 256) ws[i] = W[i];
    if (tid < 10) bs[tid] = Bv[tid];
    __syncthreads();

    const int row = blockIdx.x * 256 + tid;
    float acc[10];
    #pragma unroll
    for (int c = 0; c < 10; c++) acc[c] = bs[c];

    const float4* hp = (const float4*)(H + (size_t)row * 128);
    #pragma unroll
    for (int k4 = 0; k4 < 32; k4++) {
        const float4 hv = hp[k4];
        const int kb = k4 * 4;
        #pragma unroll
        for (int c = 0; c < 10; c++) {
            acc[c] = fmaf(hv.x, ws[(kb + 0) * 10 + c],
                     fmaf(hv.y, ws[(kb + 1) * 10 + c],
                     fmaf(hv.z, ws[(kb + 2) * 10 + c],
                     fmaf(hv.w, ws[(kb + 3) * 10 + c], acc[c]))));
        }
    }
    #pragma unroll
    for (int c = 0; c < 10; c++) {
        float s = 1.0f / (1.0f + expf(-acc[c]));
        s = fminf(fmaxf(s, 1e-10f), 1.0f - 1e-10f);
        out[(size_t)row * 10 + c] = s;
    }
}

// ---------------------------------------------------------------------------
// kernel_launch
// ---------------------------------------------------------------------------
extern "C" void kernel_launch(void* const* d_in, const int* in_sizes, int n_in,
                              void* d_out, int out_size)
{
    const float* feature = (const float*)d_in[0];
    const float* adj     = (const float*)d_in[1];
    const float* enc_w1  = (const float*)d_in[2];
    const float* enc_b1  = (const float*)d_in[3];
    const float* bn1_g   = (const float*)d_in[4];
    const float* bn1_b   = (const float*)d_in[5];
    const float* bn1_m   = (const float*)d_in[6];
    const float* bn1_v   = (const float*)d_in[7];
    const float* enc_w2  = (const float*)d_in[8];
    const float* enc_b2  = (const float*)d_in[9];
    const float* bn2_g   = (const float*)d_in[10];
    const float* bn2_b   = (const float*)d_in[11];
    const float* bn2_m   = (const float*)d_in[12];
    const float* bn2_v   = (const float*)d_in[13];
    const float* gcn1_w  = (const float*)d_in[14];
    const float* gcn1_b  = (const float*)d_in[15];
    const float* gcn2_w  = (const float*)d_in[16];
    const float* gcn2_b  = (const float*)d_in[17];
    const float* cls_w   = (const float*)d_in[18];
    const float* cls_b   = (const float*)d_in[19];
    float* out = (float*)d_out;

    float *h1, *h2, *h3, *h4, *dis;
    __nv_bfloat16 *t1h, *t1l, *t2h, *t2l;
    __nv_bfloat16 *w1h, *w1l, *w2h, *w2l, *q1h, *q1l, *q2h, *q2l;
    cudaGetSymbolAddress((void**)&h1,  g_h1);
    cudaGetSymbolAddress((void**)&h2,  g_h2);
    cudaGetSymbolAddress((void**)&h3,  g_h3);
    cudaGetSymbolAddress((void**)&h4,  g_h4);
    cudaGetSymbolAddress((void**)&dis, g_dis);
    cudaGetSymbolAddress((void**)&t1h, g_t1h);
    cudaGetSymbolAddress((void**)&t1l, g_t1l);
    cudaGetSymbolAddress((void**)&t2h, g_t2h);
    cudaGetSymbolAddress((void**)&t2l, g_t2l);
    cudaGetSymbolAddress((void**)&w1h, g_w1h);
    cudaGetSymbolAddress((void**)&w1l, g_w1l);
    cudaGetSymbolAddress((void**)&w2h, g_w2h);
    cudaGetSymbolAddress((void**)&w2l, g_w2l);
    cudaGetSymbolAddress((void**)&q1h, g_g1h);
    cudaGetSymbolAddress((void**)&q1l, g_g1l);
    cudaGetSymbolAddress((void**)&q2h, g_g2h);
    cudaGetSymbolAddress((void**)&q2l, g_g2l);

    // 1) degree scaling vector
    deg_kernel<<<NN, 256>>>(adj, dis);

    // 2) weight transpose + bf16 split (tiny)
    convT<<<(512 * 1024) / 256, 256>>>(enc_w1, 1024, 512, w1h, w1l);
    convT<<<(256 * 512)  / 256, 256>>>(enc_w2, 512,  256, w2h, w2l);
    convT<<<(256 * 256)  / 256, 256>>>(gcn1_w, 256,  256, q1h, q1l);
    convT<<<(128 * 256)  / 256, 256>>>(gcn2_w, 256,  128, q2h, q2l);

    // 3) enc1: h1 = relu(bn1(feature @ w1 + b1))   [NN x 512, K=1024]
    mma_gemm<0><<<dim3(NN / 128, 4), 256>>>(
        feature, 1024, w1h, w1l, 1024, 512, h1, nullptr, nullptr,
        enc_b1, bn1_g, bn1_b, bn1_m, bn1_v);
    // 4) enc2: h2 = relu(bn2(h1 @ w2 + b2))        [NN x 256, K=512]
    mma_gemm<0><<<dim3(NN / 128, 2), 256>>>(
        h1, 512, w2h, w2l, 512, 256, h2, nullptr, nullptr,
        enc_b2, bn2_g, bn2_b, bn2_m, bn2_v);
    // 5) t1 = dis .* (h2 @ gcn1_w) -> split [256][NN]
    mma_gemm<1><<<dim3(NN / 128, 2), 256>>>(
        h2, 256, q1h, q1l, 256, 256, nullptr, t1h, t1l,
        dis, nullptr, nullptr, nullptr, nullptr);
    // 6) h3 = relu(dis .* (adj @ t1) + gcn1_b)     [NN x 256, K=NN]
    mma_gemm<2><<<dim3(NN / 128, 2), 256>>>(
        adj, NN, t1h, t1l, NN, 256, h3, nullptr, nullptr,
        dis, gcn1_b, nullptr, nullptr, nullptr);
    // 7) t2 = dis .* (h3 @ gcn2_w) -> split [128][NN]
    mma_gemm<1><<<dim3(NN / 128, 1), 256>>>(
        h3, 256, q2h, q2l, 256, 128, nullptr, t2h, t2l,
        dis, nullptr, nullptr, nullptr, nullptr);
    // 8) h4 = relu(dis .* (adj @ t2) + gcn2_b)     [NN x 128, K=NN]
    mma_gemm<2><<<dim3(NN / 128, 1), 256>>>(
        adj, NN, t2h, t2l, NN, 128, h4, nullptr, nullptr,
        dis, gcn2_b, nullptr, nullptr, nullptr);
    // 9) classifier
    cls_kernel<<<NN / 256, 256>>>(h4, cls_w, cls_b, out);
}

// round 10
// speedup vs baseline: 1.4991x; 1.4991x over previous
#include <cuda_runtime.h>
#include <cuda_bf16.h>
#include <cstdint>

typedef unsigned long long u64;
typedef unsigned int u32;

#define NN 16384

// ---------------------------------------------------------------------------
// Scratch (static device globals — no runtime allocation allowed)
// ---------------------------------------------------------------------------
__device__ __nv_bfloat16 g_ajh[(size_t)NN * NN];   // adj split hi  [NN][NN]
__device__ __nv_bfloat16 g_ajl[(size_t)NN * NN];   // adj split lo
__device__ __nv_bfloat16 g_fh [(size_t)NN * 1024]; // feature split
__device__ __nv_bfloat16 g_fl [(size_t)NN * 1024];
__device__ __nv_bfloat16 g_h1h[(size_t)NN * 512];
__device__ __nv_bfloat16 g_h1l[(size_t)NN * 512];
__device__ __nv_bfloat16 g_h2h[(size_t)NN * 256];
__device__ __nv_bfloat16 g_h2l[(size_t)NN * 256];
__device__ __nv_bfloat16 g_h3h[(size_t)NN * 256];
__device__ __nv_bfloat16 g_h3l[(size_t)NN * 256];
__device__ float         g_h4 [(size_t)NN * 128];
__device__ float         g_dis[NN];
// B-side operands [N][K] (K-major)
__device__ __nv_bfloat16 g_t1h[(size_t)256 * NN];
__device__ __nv_bfloat16 g_t1l[(size_t)256 * NN];
__device__ __nv_bfloat16 g_t2h[(size_t)128 * NN];
__device__ __nv_bfloat16 g_t2l[(size_t)128 * NN];
__device__ __nv_bfloat16 g_w1h[(size_t)512 * 1024];
__device__ __nv_bfloat16 g_w1l[(size_t)512 * 1024];
__device__ __nv_bfloat16 g_w2h[(size_t)256 * 512];
__device__ __nv_bfloat16 g_w2l[(size_t)256 * 512];
__device__ __nv_bfloat16 g_g1h[(size_t)256 * 256];
__device__ __nv_bfloat16 g_g1l[(size_t)256 * 256];
__device__ __nv_bfloat16 g_g2h[(size_t)128 * 256];
__device__ __nv_bfloat16 g_g2l[(size_t)128 * 256];

// ---------------------------------------------------------------------------
// helpers
// ---------------------------------------------------------------------------
static __device__ __forceinline__ u32 cvt2(float lo, float hi) {
    u32 r;  // low 16 <- lo, high 16 <- hi
    asm("cvt.rn.bf16x2.f32 %0, %1, %2;" : "=r"(r) : "f"(hi), "f"(lo));
    return r;
}
static __device__ __forceinline__ u32 smem_u32(const void* p) {
    u32 a;
    asm("{ .reg .u64 t; cvta.to.shared.u64 t, %1; cvt.u32.u64 %0, t; }" : "=r"(a) : "l"(p));
    return a;
}
static __device__ __forceinline__ void cpasync16(u32 dst, const void* src) {
    asm volatile("cp.async.cg.shared.global [%0], [%1], 16;" :: "r"(dst), "l"(src));
}
static __device__ __forceinline__ void cp_commit() {
    asm volatile("cp.async.commit_group;" ::: "memory");
}
static __device__ __forceinline__ void cp_wait0() {
    asm volatile("cp.async.wait_group 0;" ::: "memory");
}
static __device__ __forceinline__ void cp_wait1() {
    asm volatile("cp.async.wait_group 1;" ::: "memory");
}
// mma.sync m16n8k16 bf16 -> f32 (base-target; tcgen05 is sm_103a-only, rejected)
static __device__ __forceinline__ void mma16816(float* d, const u32* a, const u32* b) {
    asm volatile(
        "mma.sync.aligned.m16n8k16.row.col.f32.bf16.bf16.f32 "
        "{%0,%1,%2,%3}, {%4,%5,%6,%7}, {%8,%9}, {%0,%1,%2,%3};"
        : "+f"(d[0]), "+f"(d[1]), "+f"(d[2]), "+f"(d[3])
        : "r"(a[0]), "r"(a[1]), "r"(a[2]), "r"(a[3]), "r"(b[0]), "r"(b[1]));
}

// ---------------------------------------------------------------------------
// GEMM: C-tile[128x128] = (Ah+Al)[M x K] @ (Bh+Bl)^T, all pre-split bf16.
// 3 passes: Ah*Bh + Ah*Bl + Al*Bh (fp32 accum).  BK=32, cp.async double buffer.
// smem tile rows: 32 bf16 (64B) padded to 80B -> conflict-free frag LDS.
// EPI 0: BN+ReLU -> split Oh/Ol row-major       (p0=b,p1=g,p2=beta,p3=m,p4=v)
// EPI 1: v*dis[row] -> split Oh/Ol transposed [col][NN]            (p0=dis)
// EPI 2: relu(v*dis[row]+p1[col]) -> split Oh/Ol row-major         (p0=dis)
// EPI 3: relu(v*dis[row]+p1[col]) -> fp32 C                        (p0=dis)
// ---------------------------------------------------------------------------
#define PAD   40
#define TILEB 10240                 // 128 * 80 bytes
#define BUFB  (4 * TILEB)           // Ah, Al, Bh, Bl
#define SMEMB (2 * BUFB)            // double buffered = 81920

template<int EPI>
__global__ void __launch_bounds__(256)
mma_gemm(const __nv_bfloat16* __restrict__ Ah, const __nv_bfloat16* __restrict__ Al,
         const __nv_bfloat16* __restrict__ Bh, const __nv_bfloat16* __restrict__ Bl,
         int K, int Nt, float* __restrict__ C,
         __nv_bfloat16* __restrict__ Oh, __nv_bfloat16* __restrict__ Ol,
         const float* __restrict__ p0, const float* __restrict__ p1,
         const float* __restrict__ p2, const float* __restrict__ p3,
         const float* __restrict__ p4)
{
    extern __shared__ char smem[];
    const u32 sb   = smem_u32(smem);
    const int tid  = threadIdx.x;
    const int lane = tid & 31;
    const int wid  = tid >> 5;
    const int g    = lane >> 2;
    const int t    = lane & 3;
    const int wm   = wid & 1;
    const int wn   = wid >> 1;
    const int n0   = blockIdx.x * 128;   // x = n-blocks: adjacent CTAs share A via L2
    const int m0   = blockIdx.y * 128;

    const __nv_bfloat16* srcs[4] = { Ah + (size_t)m0 * K, Al + (size_t)m0 * K,
                                     Bh + (size_t)n0 * K, Bl + (size_t)n0 * K };

    float acc[4][4][4];
    #pragma unroll
    for (int i = 0; i < 4; i++)
        #pragma unroll
        for (int j = 0; j < 4; j++)
            #pragma unroll
            for (int k = 0; k < 4; k++) acc[i][j][k] = 0.f;

    const int nch = K >> 5;

    // ---- loader: 8 x 16B cp.async per thread; tile = it>>1 is compile-time ----
    auto load_chunk = [&](int c, int b) {
        const int k0 = c << 5;
        #pragma unroll
        for (int it = 0; it < 8; ++it) {
            const int tile = it >> 1;
            const int row  = (it & 1) * 64 + (tid >> 2);
            const int q    = tid & 3;
            const __nv_bfloat16* src = srcs[tile] + (size_t)row * K + k0 + q * 8;
            cpasync16(sb + b * BUFB + tile * TILEB + row * 80 + q * 16, src);
        }
    };

    load_chunk(0, 0);
    cp_commit();

    for (int c = 0; c < nch; ++c) {
        if (c + 1 < nch) { load_chunk(c + 1, (c + 1) & 1); cp_commit(); cp_wait1(); }
        else             { cp_wait0(); }
        __syncthreads();

        const char* base = smem + (c & 1) * BUFB;
        const __nv_bfloat16* sAh = (const __nv_bfloat16*)(base);
        const __nv_bfloat16* sAl = (const __nv_bfloat16*)(base + TILEB);
        const __nv_bfloat16* sBh = (const __nv_bfloat16*)(base + 2 * TILEB);
        const __nv_bfloat16* sBl = (const __nv_bfloat16*)(base + 3 * TILEB);

        #pragma unroll
        for (int ko = 0; ko < 32; ko += 16) {
            u32 af[4][4], bh_[4][2], bl_[4][2];
            #pragma unroll
            for (int mt = 0; mt < 4; ++mt) {
                const int r = wm * 64 + mt * 16 + g;
                af[mt][0] = *(const u32*)&sAh[r * PAD + ko + 2 * t];
                af[mt][1] = *(const u32*)&sAh[(r + 8) * PAD + ko + 2 * t];
                af[mt][2] = *(const u32*)&sAh[r * PAD + ko + 8 + 2 * t];
                af[mt][3] = *(const u32*)&sAh[(r + 8) * PAD + ko + 8 + 2 * t];
            }
            #pragma unroll
            for (int nt = 0; nt < 4; ++nt) {
                const int r = wn * 32 + nt * 8 + g;
                bh_[nt][0] = *(const u32*)&sBh[r * PAD + ko + 2 * t];
                bh_[nt][1] = *(const u32*)&sBh[r * PAD + ko + 8 + 2 * t];
                bl_[nt][0] = *(const u32*)&sBl[r * PAD + ko + 2 * t];
                bl_[nt][1] = *(const u32*)&sBl[r * PAD + ko + 8 + 2 * t];
            }
            #pragma unroll
            for (int mt = 0; mt < 4; ++mt)
                #pragma unroll
                for (int nt = 0; nt < 4; ++nt) {
                    mma16816(acc[mt][nt], af[mt], bh_[nt]);
                    mma16816(acc[mt][nt], af[mt], bl_[nt]);
                }
            #pragma unroll
            for (int mt = 0; mt < 4; ++mt) {
                const int r = wm * 64 + mt * 16 + g;
                af[mt][0] = *(const u32*)&sAl[r * PAD + ko + 2 * t];
                af[mt][1] = *(const u32*)&sAl[(r + 8) * PAD + ko + 2 * t];
                af[mt][2] = *(const u32*)&sAl[r * PAD + ko + 8 + 2 * t];
                af[mt][3] = *(const u32*)&sAl[(r + 8) * PAD + ko + 8 + 2 * t];
            }
            #pragma unroll
            for (int mt = 0; mt < 4; ++mt)
                #pragma unroll
                for (int nt = 0; nt < 4; ++nt)
                    mma16816(acc[mt][nt], af[mt], bh_[nt]);
        }
        __syncthreads();   // protect buffer before it is re-filled
    }

    // ---- epilogue ----
    #pragma unroll
    for (int mt = 0; mt < 4; ++mt) {
        #pragma unroll
        for (int i2 = 0; i2 < 2; ++i2) {
            const int row = m0 + wm * 64 + mt * 16 + g + i2 * 8;
            float disv = 0.f;
            if (EPI != 0) disv = p0[row];
            #pragma unroll
            for (int nt = 0; nt < 4; ++nt) {
                const int colb = n0 + wn * 32 + nt * 8 + 2 * t;
                float v0 = acc[mt][nt][i2 * 2 + 0];
                float v1 = acc[mt][nt][i2 * 2 + 1];
                if (EPI == 0) {
                    const float s0 = p1[colb] * rsqrtf(p4[colb] + 1e-5f);
                    const float s1 = p1[colb + 1] * rsqrtf(p4[colb + 1] + 1e-5f);
                    v0 = fmaxf(fmaf(v0 + p0[colb] - p3[colb], s0, p2[colb]), 0.0f);
                    v1 = fmaxf(fmaf(v1 + p0[colb + 1] - p3[colb + 1], s1, p2[colb + 1]), 0.0f);
                } else if (EPI == 1) {
                    v0 *= disv; v1 *= disv;
                } else {
                    v0 = fmaxf(fmaf(v0, disv, p1[colb]), 0.0f);
                    v1 = fmaxf(fmaf(v1, disv, p1[colb + 1]), 0.0f);
                }
                if (EPI == 3) {
                    float2 o; o.x = v0; o.y = v1;
                    *(float2*)&C[(size_t)row * Nt + colb] = o;
                } else if (EPI == 1) {
                    const __nv_bfloat16 h0 = __float2bfloat16(v0);
                    const __nv_bfloat16 h1 = __float2bfloat16(v1);
                    Oh[(size_t)colb * NN + row] = h0;
                    Ol[(size_t)colb * NN + row] = __float2bfloat16(v0 - __bfloat162float(h0));
                    Oh[(size_t)(colb + 1) * NN + row] = h1;
                    Ol[(size_t)(colb + 1) * NN + row] = __float2bfloat16(v1 - __bfloat162float(h1));
                } else {
                    const u32 hp = cvt2(v0, v1);
                    const float r0 = v0 - __uint_as_float(hp << 16);
                    const float r1 = v1 - __uint_as_float(hp & 0xFFFF0000u);
                    *(u32*)&Oh[(size_t)row * Nt + colb] = hp;
                    *(u32*)&Ol[(size_t)row * Nt + colb] = cvt2(r0, r1);
                }
            }
        }
    }
}

// ---------------------------------------------------------------------------
// convAdj: adj fp32 -> split bf16, FUSED with degree rowsum -> dis
// ---------------------------------------------------------------------------
__global__ void convAdj(const float* __restrict__ adj, __nv_bfloat16* __restrict__ ajh,
                        __nv_bfloat16* __restrict__ ajl, float* __restrict__ dis)
{
    const int row = blockIdx.x;
    const float4* a = (const float4*)(adj + (size_t)row * NN);
    u64* oh = (u64*)(ajh + (size_t)row * NN);
    u64* ol = (u64*)(ajl + (size_t)row * NN);
    float s = 0.f;
    for (int i = threadIdx.x; i < NN / 4; i += 256) {
        const float4 v = a[i];
        s += (v.x + v.y) + (v.z + v.w);
        const u32 h01 = cvt2(v.x, v.y);
        const u32 h23 = cvt2(v.z, v.w);
        const float l0 = v.x - __uint_as_float(h01 << 16);
        const float l1 = v.y - __uint_as_float(h01 & 0xFFFF0000u);
        const float l2 = v.z - __uint_as_float(h23 << 16);
        const float l3 = v.w - __uint_as_float(h23 & 0xFFFF0000u);
        oh[i] = ((u64)h23 << 32) | h01;
        ol[i] = ((u64)cvt2(l2, l3) << 32) | cvt2(l0, l1);
    }
    __shared__ float red[256];
    red[threadIdx.x] = s;
    __syncthreads();
    #pragma unroll
    for (int st = 128; st > 0; st >>= 1) {
        if (threadIdx.x < st) red[threadIdx.x] += red[threadIdx.x + st];
        __syncthreads();
    }
    if (threadIdx.x == 0) dis[row] = rsqrtf(red[0]);
}

// ---------------------------------------------------------------------------
// convS: elementwise fp32 -> split bf16 (feature); one float4 per thread
// ---------------------------------------------------------------------------
__global__ void convS(const float* __restrict__ in, __nv_bfloat16* __restrict__ oh,
                      __nv_bfloat16* __restrict__ ol)
{
    const size_t i = (size_t)blockIdx.x * 256 + threadIdx.x;
    const float4 v = ((const float4*)in)[i];
    const u32 h01 = cvt2(v.x, v.y);
    const u32 h23 = cvt2(v.z, v.w);
    const float l0 = v.x - __uint_as_float(h01 << 16);
    const float l1 = v.y - __uint_as_float(h01 & 0xFFFF0000u);
    const float l2 = v.z - __uint_as_float(h23 << 16);
    const float l3 = v.w - __uint_as_float(h23 & 0xFFFF0000u);
    ((u64*)oh)[i] = ((u64)h23 << 32) | h01;
    ((u64*)ol)[i] = ((u64)cvt2(l2, l3) << 32) | cvt2(l0, l1);
}

// ---------------------------------------------------------------------------
// convT: weights [K][N] fp32 -> split bf16 [N][K]
// ---------------------------------------------------------------------------
__global__ void convT(const float* __restrict__ in, int K, int N,
                      __nv_bfloat16* __restrict__ oh, __nv_bfloat16* __restrict__ ol)
{
    const int j = blockIdx.x * 256 + threadIdx.x;
    const int n = j / K, k = j % K;
    const float v = in[(size_t)k * N + n];
    const __nv_bfloat16 h = __float2bfloat16(v);
    oh[j] = h;
    ol[j] = __float2bfloat16(v - __bfloat162float(h));
}

// ---------------------------------------------------------------------------
// Classifier
// ---------------------------------------------------------------------------
__global__ void cls_kernel(const float* __restrict__ H, const float* __restrict__ W,
                           const float* __restrict__ Bv, float* __restrict__ out)
{
    __shared__ float ws[128 * 10];
    __shared__ float bs[10];
    const int tid = threadIdx.x;
    for (int i = tid; i < 128 * 10; i += 256) ws[i] = W[i];
    if (tid < 10) bs[tid] = Bv[tid];
    __syncthreads();

    const int row = blockIdx.x * 256 + tid;
    float acc[10];
    #pragma unroll
    for (int c = 0; c < 10; c++) acc[c] = bs[c];

    const float4* hp = (const float4*)(H + (size_t)row * 128);
    #pragma unroll
    for (int k4 = 0; k4 < 32; k4++) {
        const float4 hv = hp[k4];
        const int kb = k4 * 4;
        #pragma unroll
        for (int c = 0; c < 10; c++) {
            acc[c] = fmaf(hv.x, ws[(kb + 0) * 10 + c],
                     fmaf(hv.y, ws[(kb + 1) * 10 + c],
                     fmaf(hv.z, ws[(kb + 2) * 10 + c],
                     fmaf(hv.w, ws[(kb + 3) * 10 + c], acc[c]))));
        }
    }
    #pragma unroll
    for (int c = 0; c < 10; c++) {
        float s = 1.0f / (1.0f + expf(-acc[c]));
        s = fminf(fmaxf(s, 1e-10f), 1.0f - 1e-10f);
        out[(size_t)row * 10 + c] = s;
    }
}

// ---------------------------------------------------------------------------
// kernel_launch
// ---------------------------------------------------------------------------
extern "C" void kernel_launch(void* const* d_in, const int* in_sizes, int n_in,
                              void* d_out, int out_size)
{
    const float* feature = (const float*)d_in[0];
    const float* adj     = (const float*)d_in[1];
    const float* enc_w1  = (const float*)d_in[2];
    const float* enc_b1  = (const float*)d_in[3];
    const float* bn1_g   = (const float*)d_in[4];
    const float* bn1_b   = (const float*)d_in[5];
    const float* bn1_m   = (const float*)d_in[6];
    const float* bn1_v   = (const float*)d_in[7];
    const float* enc_w2  = (const float*)d_in[8];
    const float* enc_b2  = (const float*)d_in[9];
    const float* bn2_g   = (const float*)d_in[10];
    const float* bn2_b   = (const float*)d_in[11];
    const float* bn2_m   = (const float*)d_in[12];
    const float* bn2_v   = (const float*)d_in[13];
    const float* gcn1_w  = (const float*)d_in[14];
    const float* gcn1_b  = (const float*)d_in[15];
    const float* gcn2_w  = (const float*)d_in[16];
    const float* gcn2_b  = (const float*)d_in[17];
    const float* cls_w   = (const float*)d_in[18];
    const float* cls_b   = (const float*)d_in[19];
    float* out = (float*)d_out;

    __nv_bfloat16 *ajh, *ajl, *fh, *fl, *h1h, *h1l, *h2h, *h2l, *h3h, *h3l;
    __nv_bfloat16 *t1h, *t1l, *t2h, *t2l;
    __nv_bfloat16 *w1h, *w1l, *w2h, *w2l, *q1h, *q1l, *q2h, *q2l;
    float *h4, *dis;
    cudaGetSymbolAddress((void**)&ajh, g_ajh);
    cudaGetSymbolAddress((void**)&ajl, g_ajl);
    cudaGetSymbolAddress((void**)&fh,  g_fh);
    cudaGetSymbolAddress((void**)&fl,  g_fl);
    cudaGetSymbolAddress((void**)&h1h, g_h1h);
    cudaGetSymbolAddress((void**)&h1l, g_h1l);
    cudaGetSymbolAddress((void**)&h2h, g_h2h);
    cudaGetSymbolAddress((void**)&h2l, g_h2l);
    cudaGetSymbolAddress((void**)&h3h, g_h3h);
    cudaGetSymbolAddress((void**)&h3l, g_h3l);
    cudaGetSymbolAddress((void**)&h4,  g_h4);
    cudaGetSymbolAddress((void**)&dis, g_dis);
    cudaGetSymbolAddress((void**)&t1h, g_t1h);
    cudaGetSymbolAddress((void**)&t1l, g_t1l);
    cudaGetSymbolAddress((void**)&t2h, g_t2h);
    cudaGetSymbolAddress((void**)&t2l, g_t2l);
    cudaGetSymbolAddress((void**)&w1h, g_w1h);
    cudaGetSymbolAddress((void**)&w1l, g_w1l);
    cudaGetSymbolAddress((void**)&w2h, g_w2h);
    cudaGetSymbolAddress((void**)&w2l, g_w2l);
    cudaGetSymbolAddress((void**)&q1h, g_g1h);
    cudaGetSymbolAddress((void**)&q1l, g_g1l);
    cudaGetSymbolAddress((void**)&q2h, g_g2h);
    cudaGetSymbolAddress((void**)&q2l, g_g2l);

    cudaFuncSetAttribute(mma_gemm<0>, cudaFuncAttributeMaxDynamicSharedMemorySize, SMEMB);
    cudaFuncSetAttribute(mma_gemm<1>, cudaFuncAttributeMaxDynamicSharedMemorySize, SMEMB);
    cudaFuncSetAttribute(mma_gemm<2>, cudaFuncAttributeMaxDynamicSharedMemorySize, SMEMB);
    cudaFuncSetAttribute(mma_gemm<3>, cudaFuncAttributeMaxDynamicSharedMemorySize, SMEMB);

    // 0: feature split
    convS<<<NN * 1024 / 1024, 256>>>(feature, fh, fl);
    // 1,2: encoder weights
    convT<<<(512 * 1024) / 256, 256>>>(enc_w1, 1024, 512, w1h, w1l);
    convT<<<(256 * 512)  / 256, 256>>>(enc_w2, 512,  256, w2h, w2l);
    // 3: enc1  h1 = relu(bn1(feature @ w1 + b1))     [NN x 512, K=1024]
    mma_gemm<0><<<dim3(4, NN / 128), 256, SMEMB>>>(
        fh, fl, w1h, w1l, 1024, 512, nullptr, h1h, h1l,
        enc_b1, bn1_g, bn1_b, bn1_m, bn1_v);
    // 4: enc2  h2 = relu(bn2(h1 @ w2 + b2))          [NN x 256, K=512]
    mma_gemm<0><<<dim3(2, NN / 128), 256, SMEMB>>>(
        h1h, h1l, w2h, w2l, 512, 256, nullptr, h2h, h2l,
        enc_b2, bn2_g, bn2_b, bn2_m, bn2_v);
    // 5: adj split + degree
    convAdj<<<NN, 256>>>(adj, ajh, ajl, dis);
    // 6: gcn1 weights
    convT<<<(256 * 256) / 256, 256>>>(gcn1_w, 256, 256, q1h, q1l);
    // 7: t1 = dis .* (h2 @ gcn1_w)  -> split [256][NN]
    mma_gemm<1><<<dim3(2, NN / 128), 256, SMEMB>>>(
        h2h, h2l, q1h, q1l, 256, 256, nullptr, t1h, t1l,
        dis, nullptr, nullptr, nullptr, nullptr);
    // 8: h3 = relu(dis .* (adj @ t1) + gcn1_b)  -> split row-major
    mma_gemm<2><<<dim3(2, NN / 128), 256, SMEMB>>>(
        ajh, ajl, t1h, t1l, NN, 256, nullptr, h3h, h3l,
        dis, gcn1_b, nullptr, nullptr, nullptr);
    // 9: gcn2 weights
    convT<<<(128 * 256) / 256, 256>>>(gcn2_w, 256, 128, q2h, q2l);
    // 10: t2 = dis .* (h3 @ gcn2_w) -> split [128][NN]
    mma_gemm<1><<<dim3(1, NN / 128), 256, SMEMB>>>(
        h3h, h3l, q2h, q2l, 256, 128, nullptr, t2h, t2l,
        dis, nullptr, nullptr, nullptr, nullptr);
    // 11: h4 = relu(dis .* (adj @ t2) + gcn2_b) -> fp32
    mma_gemm<3><<<dim3(1, NN / 128), 256, SMEMB>>>(
        ajh, ajl, t2h, t2l, NN, 128, h4, nullptr, nullptr,
        dis, gcn2_b, nullptr, nullptr, nullptr);
    // 12: classifier
    cls_kernel<<<NN / 256, 256>>>(h4, cls_w, cls_b, out);
}

// round 11
// speedup vs baseline: 1.5568x; 1.0385x over previous
#include <cuda_runtime.h>
#include <cuda_bf16.h>
#include <cstdint>

typedef unsigned long long u64;
typedef unsigned int u32;

#define NN 16384

// ---------------------------------------------------------------------------
// Scratch (static device globals — no runtime allocation allowed)
// ---------------------------------------------------------------------------
__device__ __nv_bfloat16 g_ajh[(size_t)NN * NN];   // adj split hi  [NN][NN]
__device__ __nv_bfloat16 g_ajl[(size_t)NN * NN];   // adj split lo
__device__ __nv_bfloat16 g_fh [(size_t)NN * 1024]; // feature split
__device__ __nv_bfloat16 g_fl [(size_t)NN * 1024];
__device__ __nv_bfloat16 g_h1h[(size_t)NN * 512];
__device__ __nv_bfloat16 g_h1l[(size_t)NN * 512];
__device__ __nv_bfloat16 g_h2h[(size_t)NN * 256];
__device__ __nv_bfloat16 g_h2l[(size_t)NN * 256];
__device__ __nv_bfloat16 g_h3h[(size_t)NN * 256];
__device__ __nv_bfloat16 g_h3l[(size_t)NN * 256];
__device__ float         g_h4 [(size_t)NN * 128];
__device__ float         g_dis[NN];
// B-side operands [N][K] (K-major)
__device__ __nv_bfloat16 g_t1h[(size_t)256 * NN];
__device__ __nv_bfloat16 g_t1l[(size_t)256 * NN];
__device__ __nv_bfloat16 g_t2h[(size_t)128 * NN];
__device__ __nv_bfloat16 g_t2l[(size_t)128 * NN];
__device__ __nv_bfloat16 g_w1h[(size_t)512 * 1024];
__device__ __nv_bfloat16 g_w1l[(size_t)512 * 1024];
__device__ __nv_bfloat16 g_w2h[(size_t)256 * 512];
__device__ __nv_bfloat16 g_w2l[(size_t)256 * 512];
__device__ __nv_bfloat16 g_g1h[(size_t)256 * 256];
__device__ __nv_bfloat16 g_g1l[(size_t)256 * 256];
__device__ __nv_bfloat16 g_g2h[(size_t)128 * 256];
__device__ __nv_bfloat16 g_g2l[(size_t)128 * 256];

// ---------------------------------------------------------------------------
// helpers
// ---------------------------------------------------------------------------
static __device__ __forceinline__ u32 cvt2(float lo, float hi) {
    u32 r;  // low 16 <- lo, high 16 <- hi
    asm("cvt.rn.bf16x2.f32 %0, %1, %2;" : "=r"(r) : "f"(hi), "f"(lo));
    return r;
}
static __device__ __forceinline__ u32 smem_u32(const void* p) {
    u32 a;
    asm("{ .reg .u64 t; cvta.to.shared.u64 t, %1; cvt.u32.u64 %0, t; }" : "=r"(a) : "l"(p));
    return a;
}
static __device__ __forceinline__ void cpasync16(u32 dst, const void* src) {
    asm volatile("cp.async.cg.shared.global [%0], [%1], 16;" :: "r"(dst), "l"(src));
}
static __device__ __forceinline__ void cp_commit() {
    asm volatile("cp.async.commit_group;" ::: "memory");
}
static __device__ __forceinline__ void cp_wait0() {
    asm volatile("cp.async.wait_group 0;" ::: "memory");
}
static __device__ __forceinline__ void cp_wait1() {
    asm volatile("cp.async.wait_group 1;" ::: "memory");
}
// mma.sync m16n8k16 bf16 -> f32 (base-target; tcgen05 is sm_103a-only, rejected)
static __device__ __forceinline__ void mma16816(float* d, const u32* a, const u32* b) {
    asm volatile(
        "mma.sync.aligned.m16n8k16.row.col.f32.bf16.bf16.f32 "
        "{%0,%1,%2,%3}, {%4,%5,%6,%7}, {%8,%9}, {%0,%1,%2,%3};"
        : "+f"(d[0]), "+f"(d[1]), "+f"(d[2]), "+f"(d[3])
        : "r"(a[0]), "r"(a[1]), "r"(a[2]), "r"(a[3]), "r"(b[0]), "r"(b[1]));
}

// ---------------------------------------------------------------------------
// GEMM: C-tile[128x128] = (Ah+Al)[M x K] @ (Bh+Bl)^T, all pre-split bf16.
// 3 passes: Ah*Bh + Ah*Bl + Al*Bh (fp32 accum).  BK=32, cp.async double buffer.
// __launch_bounds__(256,2): cap 128 regs -> 2 CTAs/SM (was 148 regs, 1 CTA/SM,
// occ 12.4%, tensor 42.9% — latency windows had nothing to overlap with).
// EPI 0: BN+ReLU -> split Oh/Ol row-major       (p0=b,p1=g,p2=beta,p3=m,p4=v)
// EPI 1: v*dis[row] -> split Oh/Ol transposed [col][NN]            (p0=dis)
// EPI 2: relu(v*dis[row]+p1[col]) -> split Oh/Ol row-major         (p0=dis)
// EPI 3: relu(v*dis[row]+p1[col]) -> fp32 C                        (p0=dis)
// ---------------------------------------------------------------------------
#define PAD   40
#define TILEB 10240                 // 128 * 80 bytes
#define BUFB  (4 * TILEB)           // Ah, Al, Bh, Bl
#define SMEMB (2 * BUFB)            // double buffered = 81920

template<int EPI>
__global__ void __launch_bounds__(256, 2)
mma_gemm(const __nv_bfloat16* __restrict__ Ah, const __nv_bfloat16* __restrict__ Al,
         const __nv_bfloat16* __restrict__ Bh, const __nv_bfloat16* __restrict__ Bl,
         int K, int Nt, float* __restrict__ C,
         __nv_bfloat16* __restrict__ Oh, __nv_bfloat16* __restrict__ Ol,
         const float* __restrict__ p0, const float* __restrict__ p1,
         const float* __restrict__ p2, const float* __restrict__ p3,
         const float* __restrict__ p4)
{
    extern __shared__ char smem[];
    const u32 sb   = smem_u32(smem);
    const int tid  = threadIdx.x;
    const int lane = tid & 31;
    const int wid  = tid >> 5;
    const int g    = lane >> 2;
    const int t    = lane & 3;
    const int wm   = wid & 1;
    const int wn   = wid >> 1;
    const int n0   = blockIdx.x * 128;   // x = n-blocks: adjacent CTAs share A via L2
    const int m0   = blockIdx.y * 128;

    const __nv_bfloat16* srcs[4] = { Ah + (size_t)m0 * K, Al + (size_t)m0 * K,
                                     Bh + (size_t)n0 * K, Bl + (size_t)n0 * K };

    float acc[4][4][4];
    #pragma unroll
    for (int i = 0; i < 4; i++)
        #pragma unroll
        for (int j = 0; j < 4; j++)
            #pragma unroll
            for (int k = 0; k < 4; k++) acc[i][j][k] = 0.f;

    const int nch = K >> 5;

    // ---- loader: 8 x 16B cp.async per thread; tile = it>>1 is compile-time ----
    auto load_chunk = [&](int c, int b) {
        const int k0 = c << 5;
        #pragma unroll
        for (int it = 0; it < 8; ++it) {
            const int tile = it >> 1;
            const int row  = (it & 1) * 64 + (tid >> 2);
            const int q    = tid & 3;
            const __nv_bfloat16* src = srcs[tile] + (size_t)row * K + k0 + q * 8;
            cpasync16(sb + b * BUFB + tile * TILEB + row * 80 + q * 16, src);
        }
    };

    load_chunk(0, 0);
    cp_commit();

    for (int c = 0; c < nch; ++c) {
        if (c + 1 < nch) { load_chunk(c + 1, (c + 1) & 1); cp_commit(); cp_wait1(); }
        else             { cp_wait0(); }
        __syncthreads();

        const char* base = smem + (c & 1) * BUFB;
        const __nv_bfloat16* sAh = (const __nv_bfloat16*)(base);
        const __nv_bfloat16* sAl = (const __nv_bfloat16*)(base + TILEB);
        const __nv_bfloat16* sBh = (const __nv_bfloat16*)(base + 2 * TILEB);
        const __nv_bfloat16* sBl = (const __nv_bfloat16*)(base + 3 * TILEB);

        #pragma unroll
        for (int ko = 0; ko < 32; ko += 16) {
            u32 af[4][4], bh_[4][2], bl_[4][2];
            #pragma unroll
            for (int mt = 0; mt < 4; ++mt) {
                const int r = wm * 64 + mt * 16 + g;
                af[mt][0] = *(const u32*)&sAh[r * PAD + ko + 2 * t];
                af[mt][1] = *(const u32*)&sAh[(r + 8) * PAD + ko + 2 * t];
                af[mt][2] = *(const u32*)&sAh[r * PAD + ko + 8 + 2 * t];
                af[mt][3] = *(const u32*)&sAh[(r + 8) * PAD + ko + 8 + 2 * t];
            }
            #pragma unroll
            for (int nt = 0; nt < 4; ++nt) {
                const int r = wn * 32 + nt * 8 + g;
                bh_[nt][0] = *(const u32*)&sBh[r * PAD + ko + 2 * t];
                bh_[nt][1] = *(const u32*)&sBh[r * PAD + ko + 8 + 2 * t];
                bl_[nt][0] = *(const u32*)&sBl[r * PAD + ko + 2 * t];
                bl_[nt][1] = *(const u32*)&sBl[r * PAD + ko + 8 + 2 * t];
            }
            #pragma unroll
            for (int mt = 0; mt < 4; ++mt)
                #pragma unroll
                for (int nt = 0; nt < 4; ++nt) {
                    mma16816(acc[mt][nt], af[mt], bh_[nt]);
                    mma16816(acc[mt][nt], af[mt], bl_[nt]);
                }
            #pragma unroll
            for (int mt = 0; mt < 4; ++mt) {
                const int r = wm * 64 + mt * 16 + g;
                af[mt][0] = *(const u32*)&sAl[r * PAD + ko + 2 * t];
                af[mt][1] = *(const u32*)&sAl[(r + 8) * PAD + ko + 2 * t];
                af[mt][2] = *(const u32*)&sAl[r * PAD + ko + 8 + 2 * t];
                af[mt][3] = *(const u32*)&sAl[(r + 8) * PAD + ko + 8 + 2 * t];
            }
            #pragma unroll
            for (int mt = 0; mt < 4; ++mt)
                #pragma unroll
                for (int nt = 0; nt < 4; ++nt)
                    mma16816(acc[mt][nt], af[mt], bh_[nt]);
        }
        __syncthreads();   // protect buffer before it is re-filled
    }

    // ---- epilogue ----
    #pragma unroll
    for (int mt = 0; mt < 4; ++mt) {
        #pragma unroll
        for (int i2 = 0; i2 < 2; ++i2) {
            const int row = m0 + wm * 64 + mt * 16 + g + i2 * 8;
            float disv = 0.f;
            if (EPI != 0) disv = p0[row];
            #pragma unroll
            for (int nt = 0; nt < 4; ++nt) {
                const int colb = n0 + wn * 32 + nt * 8 + 2 * t;
                float v0 = acc[mt][nt][i2 * 2 + 0];
                float v1 = acc[mt][nt][i2 * 2 + 1];
                if (EPI == 0) {
                    const float s0 = p1[colb] * rsqrtf(p4[colb] + 1e-5f);
                    const float s1 = p1[colb + 1] * rsqrtf(p4[colb + 1] + 1e-5f);
                    v0 = fmaxf(fmaf(v0 + p0[colb] - p3[colb], s0, p2[colb]), 0.0f);
                    v1 = fmaxf(fmaf(v1 + p0[colb + 1] - p3[colb + 1], s1, p2[colb + 1]), 0.0f);
                } else if (EPI == 1) {
                    v0 *= disv; v1 *= disv;
                } else {
                    v0 = fmaxf(fmaf(v0, disv, p1[colb]), 0.0f);
                    v1 = fmaxf(fmaf(v1, disv, p1[colb + 1]), 0.0f);
                }
                if (EPI == 3) {
                    float2 o; o.x = v0; o.y = v1;
                    *(float2*)&C[(size_t)row * Nt + colb] = o;
                } else if (EPI == 1) {
                    const __nv_bfloat16 h0 = __float2bfloat16(v0);
                    const __nv_bfloat16 h1 = __float2bfloat16(v1);
                    Oh[(size_t)colb * NN + row] = h0;
                    Ol[(size_t)colb * NN + row] = __float2bfloat16(v0 - __bfloat162float(h0));
                    Oh[(size_t)(colb + 1) * NN + row] = h1;
                    Ol[(size_t)(colb + 1) * NN + row] = __float2bfloat16(v1 - __bfloat162float(h1));
                } else {
                    const u32 hp = cvt2(v0, v1);
                    const float r0 = v0 - __uint_as_float(hp << 16);
                    const float r1 = v1 - __uint_as_float(hp & 0xFFFF0000u);
                    *(u32*)&Oh[(size_t)row * Nt + colb] = hp;
                    *(u32*)&Ol[(size_t)row * Nt + colb] = cvt2(r0, r1);
                }
            }
        }
    }
}

// ---------------------------------------------------------------------------
// convAdj: adj fp32 -> split bf16, FUSED with degree rowsum -> dis
// ---------------------------------------------------------------------------
__global__ void convAdj(const float* __restrict__ adj, __nv_bfloat16* __restrict__ ajh,
                        __nv_bfloat16* __restrict__ ajl, float* __restrict__ dis)
{
    const int row = blockIdx.x;
    const float4* a = (const float4*)(adj + (size_t)row * NN);
    u64* oh = (u64*)(ajh + (size_t)row * NN);
    u64* ol = (u64*)(ajl + (size_t)row * NN);
    float s = 0.f;
    for (int i = threadIdx.x; i < NN / 4; i += 256) {
        const float4 v = a[i];
        s += (v.x + v.y) + (v.z + v.w);
        const u32 h01 = cvt2(v.x, v.y);
        const u32 h23 = cvt2(v.z, v.w);
        const float l0 = v.x - __uint_as_float(h01 << 16);
        const float l1 = v.y - __uint_as_float(h01 & 0xFFFF0000u);
        const float l2 = v.z - __uint_as_float(h23 << 16);
        const float l3 = v.w - __uint_as_float(h23 & 0xFFFF0000u);
        oh[i] = ((u64)h23 << 32) | h01;
        ol[i] = ((u64)cvt2(l2, l3) << 32) | cvt2(l0, l1);
    }
    __shared__ float red[256];
    red[threadIdx.x] = s;
    __syncthreads();
    #pragma unroll
    for (int st = 128; st > 0; st >>= 1) {
        if (threadIdx.x < st) red[threadIdx.x] += red[threadIdx.x + st];
        __syncthreads();
    }
    if (threadIdx.x == 0) dis[row] = rsqrtf(red[0]);
}

// ---------------------------------------------------------------------------
// convS: elementwise fp32 -> split bf16 (feature); one float4 per thread
// ---------------------------------------------------------------------------
__global__ void convS(const float* __restrict__ in, __nv_bfloat16* __restrict__ oh,
                      __nv_bfloat16* __restrict__ ol)
{
    const size_t i = (size_t)blockIdx.x * 256 + threadIdx.x;
    const float4 v = ((const float4*)in)[i];
    const u32 h01 = cvt2(v.x, v.y);
    const u32 h23 = cvt2(v.z, v.w);
    const float l0 = v.x - __uint_as_float(h01 << 16);
    const float l1 = v.y - __uint_as_float(h01 & 0xFFFF0000u);
    const float l2 = v.z - __uint_as_float(h23 << 16);
    const float l3 = v.w - __uint_as_float(h23 & 0xFFFF0000u);
    ((u64*)oh)[i] = ((u64)h23 << 32) | h01;
    ((u64*)ol)[i] = ((u64)cvt2(l2, l3) << 32) | cvt2(l0, l1);
}

// ---------------------------------------------------------------------------
// convT: weights [K][N] fp32 -> split bf16 [N][K]
// ---------------------------------------------------------------------------
__global__ void convT(const float* __restrict__ in, int K, int N,
                      __nv_bfloat16* __restrict__ oh, __nv_bfloat16* __restrict__ ol)
{
    const int j = blockIdx.x * 256 + threadIdx.x;
    const int n = j / K, k = j % K;
    const float v = in[(size_t)k * N + n];
    const __nv_bfloat16 h = __float2bfloat16(v);
    oh[j] = h;
    ol[j] = __float2bfloat16(v - __bfloat162float(h));
}

// ---------------------------------------------------------------------------
// Classifier
// ---------------------------------------------------------------------------
__global__ void cls_kernel(const float* __restrict__ H, const float* __restrict__ W,
                           const float* __restrict__ Bv, float* __restrict__ out)
{
    __shared__ float ws[128 * 10];
    __shared__ float bs[10];
    const int tid = threadIdx.x;
    for (int i = tid; i < 128 * 10; i += 256) ws[i] = W[i];
    if (tid < 10) bs[tid] = Bv[tid];
    __syncthreads();

    const int row = blockIdx.x * 256 + tid;
    float acc[10];
    #pragma unroll
    for (int c = 0; c < 10; c++) acc[c] = bs[c];

    const float4* hp = (const float4*)(H + (size_t)row * 128);
    #pragma unroll
    for (int k4 = 0; k4 < 32; k4++) {
        const float4 hv = hp[k4];
        const int kb = k4 * 4;
        #pragma unroll
        for (int c = 0; c < 10; c++) {
            acc[c] = fmaf(hv.x, ws[(kb + 0) * 10 + c],
                     fmaf(hv.y, ws[(kb + 1) * 10 + c],
                     fmaf(hv.z, ws[(kb + 2) * 10 + c],
                     fmaf(hv.w, ws[(kb + 3) * 10 + c], acc[c]))));
        }
    }
    #pragma unroll
    for (int c = 0; c < 10; c++) {
        float s = 1.0f / (1.0f + expf(-acc[c]));
        s = fminf(fmaxf(s, 1e-10f), 1.0f - 1e-10f);
        out[(size_t)row * 10 + c] = s;
    }
}

// ---------------------------------------------------------------------------
// kernel_launch
// ---------------------------------------------------------------------------
extern "C" void kernel_launch(void* const* d_in, const int* in_sizes, int n_in,
                              void* d_out, int out_size)
{
    const float* feature = (const float*)d_in[0];
    const float* adj     = (const float*)d_in[1];
    const float* enc_w1  = (const float*)d_in[2];
    const float* enc_b1  = (const float*)d_in[3];
    const float* bn1_g   = (const float*)d_in[4];
    const float* bn1_b   = (const float*)d_in[5];
    const float* bn1_m   = (const float*)d_in[6];
    const float* bn1_v   = (const float*)d_in[7];
    const float* enc_w2  = (const float*)d_in[8];
    const float* enc_b2  = (const float*)d_in[9];
    const float* bn2_g   = (const float*)d_in[10];
    const float* bn2_b   = (const float*)d_in[11];
    const float* bn2_m   = (const float*)d_in[12];
    const float* bn2_v   = (const float*)d_in[13];
    const float* gcn1_w  = (const float*)d_in[14];
    const float* gcn1_b  = (const float*)d_in[15];
    const float* gcn2_w  = (const float*)d_in[16];
    const float* gcn2_b  = (const float*)d_in[17];
    const float* cls_w   = (const float*)d_in[18];
    const float* cls_b   = (const float*)d_in[19];
    float* out = (float*)d_out;

    __nv_bfloat16 *ajh, *ajl, *fh, *fl, *h1h, *h1l, *h2h, *h2l, *h3h, *h3l;
    __nv_bfloat16 *t1h, *t1l, *t2h, *t2l;
    __nv_bfloat16 *w1h, *w1l, *w2h, *w2l, *q1h, *q1l, *q2h, *q2l;
    float *h4, *dis;
    cudaGetSymbolAddress((void**)&ajh, g_ajh);
    cudaGetSymbolAddress((void**)&ajl, g_ajl);
    cudaGetSymbolAddress((void**)&fh,  g_fh);
    cudaGetSymbolAddress((void**)&fl,  g_fl);
    cudaGetSymbolAddress((void**)&h1h, g_h1h);
    cudaGetSymbolAddress((void**)&h1l, g_h1l);
    cudaGetSymbolAddress((void**)&h2h, g_h2h);
    cudaGetSymbolAddress((void**)&h2l, g_h2l);
    cudaGetSymbolAddress((void**)&h3h, g_h3h);
    cudaGetSymbolAddress((void**)&h3l, g_h3l);
    cudaGetSymbolAddress((void**)&h4,  g_h4);
    cudaGetSymbolAddress((void**)&dis, g_dis);
    cudaGetSymbolAddress((void**)&t1h, g_t1h);
    cudaGetSymbolAddress((void**)&t1l, g_t1l);
    cudaGetSymbolAddress((void**)&t2h, g_t2h);
    cudaGetSymbolAddress((void**)&t2l, g_t2l);
    cudaGetSymbolAddress((void**)&w1h, g_w1h);
    cudaGetSymbolAddress((void**)&w1l, g_w1l);
    cudaGetSymbolAddress((void**)&w2h, g_w2h);
    cudaGetSymbolAddress((void**)&w2l, g_w2l);
    cudaGetSymbolAddress((void**)&q1h, g_g1h);
    cudaGetSymbolAddress((void**)&q1l, g_g1l);
    cudaGetSymbolAddress((void**)&q2h, g_g2h);
    cudaGetSymbolAddress((void**)&q2l, g_g2l);

    cudaFuncSetAttribute(mma_gemm<0>, cudaFuncAttributeMaxDynamicSharedMemorySize, SMEMB);
    cudaFuncSetAttribute(mma_gemm<1>, cudaFuncAttributeMaxDynamicSharedMemorySize, SMEMB);
    cudaFuncSetAttribute(mma_gemm<2>, cudaFuncAttributeMaxDynamicSharedMemorySize, SMEMB);
    cudaFuncSetAttribute(mma_gemm<3>, cudaFuncAttributeMaxDynamicSharedMemorySize, SMEMB);

    // 0: feature split
    convS<<<NN * 1024 / 1024, 256>>>(feature, fh, fl);
    // 1,2: encoder weights
    convT<<<(512 * 1024) / 256, 256>>>(enc_w1, 1024, 512, w1h, w1l);
    convT<<<(256 * 512)  / 256, 256>>>(enc_w2, 512,  256, w2h, w2l);
    // 3: enc1  h1 = relu(bn1(feature @ w1 + b1))     [NN x 512, K=1024]
    mma_gemm<0><<<dim3(4, NN / 128), 256, SMEMB>>>(
        fh, fl, w1h, w1l, 1024, 512, nullptr, h1h, h1l,
        enc_b1, bn1_g, bn1_b, bn1_m, bn1_v);
    // 4: enc2  h2 = relu(bn2(h1 @ w2 + b2))          [NN x 256, K=512]
    mma_gemm<0><<<dim3(2, NN / 128), 256, SMEMB>>>(
        h1h, h1l, w2h, w2l, 512, 256, nullptr, h2h, h2l,
        enc_b2, bn2_g, bn2_b, bn2_m, bn2_v);
    // 5: adj split + degree
    convAdj<<<NN, 256>>>(adj, ajh, ajl, dis);
    // 6: gcn1 weights
    convT<<<(256 * 256) / 256, 256>>>(gcn1_w, 256, 256, q1h, q1l);
    // 7: t1 = dis .* (h2 @ gcn1_w)  -> split [256][NN]
    mma_gemm<1><<<dim3(2, NN / 128), 256, SMEMB>>>(
        h2h, h2l, q1h, q1l, 256, 256, nullptr, t1h, t1l,
        dis, nullptr, nullptr, nullptr, nullptr);
    // 8: h3 = relu(dis .* (adj @ t1) + gcn1_b)  -> split row-major
    mma_gemm<2><<<dim3(2, NN / 128), 256, SMEMB>>>(
        ajh, ajl, t1h, t1l, NN, 256, nullptr, h3h, h3l,
        dis, gcn1_b, nullptr, nullptr, nullptr);
    // 9: gcn2 weights
    convT<<<(128 * 256) / 256, 256>>>(gcn2_w, 256, 128, q2h, q2l);
    // 10: t2 = dis .* (h3 @ gcn2_w) -> split [128][NN]
    mma_gemm<1><<<dim3(1, NN / 128), 256, SMEMB>>>(
        h3h, h3l, q2h, q2l, 256, 128, nullptr, t2h, t2l,
        dis, nullptr, nullptr, nullptr, nullptr);
    // 11: h4 = relu(dis .* (adj @ t2) + gcn2_b) -> fp32
    mma_gemm<3><<<dim3(1, NN / 128), 256, SMEMB>>>(
        ajh, ajl, t2h, t2l, NN, 128, h4, nullptr, nullptr,
        dis, gcn2_b, nullptr, nullptr, nullptr);
    // 12: classifier
    cls_kernel<<<NN / 256, 256>>>(h4, cls_w, cls_b, out);
}